// round 4
// baseline (speedup 1.0000x reference)
#include <cuda_runtime.h>

// Shapes: field/gt_field (8,4,64,128,64) f32, ct/gt_ct (8,1) f32, sdf (8,1,64,128,64) f32.
// Output: scalar f32 total loss.
// One thread per spatial point (scalar loads, high occupancy), single fused
// kernel with last-block finalize.

#define NB 8
#define ND 64
#define NH 128
#define NW 64
#define SP (ND*NH*NW)
#define CS SP
#define NPTS (NB*SP)           // 4194304
#define NBLK (NPTS/256)        // 16384 blocks

#define DXd ((2.0 + 0.5) / 63.0)
#define DYd ((0.5 + 0.5) / 127.0)
#define DZd ((0.3 + 0.5) / 63.0)

__device__ __constant__ float c_inv2dx = (float)(1.0 / (2.0 * DXd));
__device__ __constant__ float c_inv2dy = (float)(1.0 / (2.0 * DYd));
__device__ __constant__ float c_inv2dz = (float)(1.0 / (2.0 * DZd));
__device__ __constant__ float c_idx2   = (float)(1.0 / (DXd * DXd));
__device__ __constant__ float c_idy2   = (float)(1.0 / (DYd * DYd));
__device__ __constant__ float c_idz2   = (float)(1.0 / (DZd * DZd));

__device__ __constant__ float c_sc_field  = (float)(1.0  / (double)(NB*4*SP));
__device__ __constant__ float c_sc_ct     = (float)(10.0 / 8.0);
__device__ __constant__ float c_sc_cm     = (float)(1.0  / (double)(NB*(ND-2)*(NH-2)*(NW-2)));
__device__ __constant__ float c_sc_noslip = (float)(10.0 / (double)NPTS);
__device__ __constant__ float c_sc_inlet  = (float)(5.0  / (double)(NB*ND*NH));
__device__ __constant__ float c_sc_outlet = (float)(1.0  / (double)(NB*ND*NH));

#define INV_RE 1.0e-6f
#define OY NW
#define OZ (NH*NW)

__device__ double g_acc = 0.0;
__device__ unsigned int g_count = 0;

__global__ void __launch_bounds__(256, 4) k_loss(
    const float* __restrict__ field,
    const float* __restrict__ ct,
    const float* __restrict__ gt_field,
    const float* __restrict__ gt_ct,
    const float* __restrict__ sdf,
    float* __restrict__ out)
{
    const int gid = blockIdx.x * 256 + threadIdx.x;   // exactly NPTS threads
    const int w = gid & (NW - 1);
    const int h = (gid >> 6) & (NH - 1);
    const int d = (gid >> 13) & (ND - 1);
    const int b = gid >> 19;

    float acc = 0.0f;

    if (gid < 8) {
        float dct = ct[gid] - gt_ct[gid];
        acc += c_sc_ct * dct * dct;
    }

    const int sidx  = (d * NH + h) * NW + w;
    const float* fb = field    + b * (4 * SP) + sidx;
    const float* gb = gt_field + b * (4 * SP) + sidx;

    // center values
    const float u  = fb[0];
    const float v  = fb[CS];
    const float wv = fb[2 * CS];
    const float p  = fb[3 * CS];

    // field MSE
    {
        float a0 = u  - gb[0];
        float a1 = v  - gb[CS];
        float a2 = wv - gb[2 * CS];
        float a3 = p  - gb[3 * CS];
        acc += c_sc_field * (a0*a0 + a1*a1 + a2*a2 + a3*a3);
    }

    const float s = sdf[b * SP + sidx];
    const float vel2 = u*u + v*v + wv*wv;

    // no-slip on solid (sdf <= 0)
    acc += (s <= 0.0f) ? c_sc_noslip * vel2 : 0.0f;

    // inlet plane w == 0
    if (w == 0) {
        float du0 = u - 1.0f;
        acc += c_sc_inlet * (du0*du0 + v*v + wv*wv);
    }

    // outlet plane w == NW-1 vs NW-2
    if (w == NW - 1) {
        float a0 = u  - fb[-1];
        float a1 = v  - fb[CS - 1];
        float a2 = wv - fb[2 * CS - 1];
        acc += c_sc_outlet * (a0*a0 + a1*a1 + a2*a2);
    }

    // interior: continuity + momentum (fluid-masked, branch-free mask)
    const bool interior = (w >= 1) & (w <= NW - 2) & (h >= 1) & (h <= NH - 2)
                        & (d >= 1) & (d <= ND - 2);
    if (interior) {
        const float m = (s > 0.0f) ? 1.0f : 0.0f;

        // batched neighbor loads (maximize MLP)
        float uxp = fb[1],         uxm = fb[-1];
        float uyp = fb[OY],        uym = fb[-OY];
        float uzp = fb[OZ],        uzm = fb[-OZ];

        float vxp = fb[CS + 1],    vxm = fb[CS - 1];
        float vyp = fb[CS + OY],   vym = fb[CS - OY];
        float vzp = fb[CS + OZ],   vzm = fb[CS - OZ];

        float wxp = fb[2*CS + 1],  wxm = fb[2*CS - 1];
        float wyp = fb[2*CS + OY], wym = fb[2*CS - OY];
        float wzp = fb[2*CS + OZ], wzm = fb[2*CS - OZ];

        float pxp = fb[3*CS + 1],  pxm = fb[3*CS - 1];
        float pyp = fb[3*CS + OY], pym = fb[3*CS - OY];
        float pzp = fb[3*CS + OZ], pzm = fb[3*CS - OZ];

        float du_dx = (uxp - uxm) * c_inv2dx;
        float du_dy = (uyp - uym) * c_inv2dy;
        float du_dz = (uzp - uzm) * c_inv2dz;

        float dv_dx = (vxp - vxm) * c_inv2dx;
        float dv_dy = (vyp - vym) * c_inv2dy;
        float dv_dz = (vzp - vzm) * c_inv2dz;

        float dw_dx = (wxp - wxm) * c_inv2dx;
        float dw_dy = (wyp - wym) * c_inv2dy;
        float dw_dz = (wzp - wzm) * c_inv2dz;

        float dp_dx = (pxp - pxm) * c_inv2dx;
        float dp_dy = (pyp - pym) * c_inv2dy;
        float dp_dz = (pzp - pzm) * c_inv2dz;

        float div = du_dx + dv_dy + dw_dz;

        float lap_u = (uxp - 2.0f*u  + uxm) * c_idx2
                    + (uyp - 2.0f*u  + uym) * c_idy2
                    + (uzp - 2.0f*u  + uzm) * c_idz2;
        float lap_v = (vxp - 2.0f*v  + vxm) * c_idx2
                    + (vyp - 2.0f*v  + vym) * c_idy2
                    + (vzp - 2.0f*v  + vzm) * c_idz2;
        float lap_w = (wxp - 2.0f*wv + wxm) * c_idx2
                    + (wyp - 2.0f*wv + wym) * c_idy2
                    + (wzp - 2.0f*wv + wzm) * c_idz2;

        float rx = u*du_dx + v*du_dy + wv*du_dz + dp_dx - INV_RE*lap_u;
        float ry = u*dv_dx + v*dv_dy + wv*dv_dz + dp_dy - INV_RE*lap_v;
        float rz = u*dw_dx + v*dw_dy + wv*dw_dz + dp_dz - INV_RE*lap_w;

        acc += (c_sc_cm * m) * (div*div + rx*rx + ry*ry + rz*rz);
    }

    // ---- reduction: warp shfl (f32) -> block (f64) -> global atomic ----
    #pragma unroll
    for (int o = 16; o > 0; o >>= 1)
        acc += __shfl_down_sync(0xffffffffu, acc, o);

    __shared__ double warpsum[8];
    if ((threadIdx.x & 31) == 0)
        warpsum[threadIdx.x >> 5] = (double)acc;
    __syncthreads();

    if (threadIdx.x == 0) {
        double t = 0.0;
        #pragma unroll
        for (int i = 0; i < 8; i++) t += warpsum[i];
        atomicAdd(&g_acc, t);
        __threadfence();
        unsigned int ticket = atomicAdd(&g_count, 1u);
        if (ticket == (unsigned)(gridDim.x - 1)) {
            double tot = atomicAdd(&g_acc, 0.0);
            out[0] = (float)tot;
            g_acc = 0.0;       // reset for next graph replay
            g_count = 0u;
            __threadfence();
        }
    }
}

extern "C" void kernel_launch(void* const* d_in, const int* in_sizes, int n_in,
                              void* d_out, int out_size)
{
    const float* field    = (const float*)d_in[0];
    const float* ct       = (const float*)d_in[1];
    const float* gt_field = (const float*)d_in[2];
    const float* gt_ct    = (const float*)d_in[3];
    const float* sdf      = (const float*)d_in[4];

    k_loss<<<NBLK, 256>>>(field, ct, gt_field, gt_ct, sdf, (float*)d_out);
}

// round 5
// speedup vs baseline: 1.3970x; 1.3970x over previous
#include <cuda_runtime.h>

// Shapes: field/gt_field (8,4,64,128,64) f32, ct/gt_ct (8,1) f32, sdf (8,1,64,128,64) f32.
// Output: scalar f32 total loss. Single fused kernel, float4 along W,
// channel-streamed interior, early-dead pressure regs, forced 4 CTAs/SM.

#define NB 8
#define ND 64
#define NH 128
#define NW 64
#define SP (ND*NH*NW)
#define CS SP
#define NPTS (NB*SP)
#define NVEC (NPTS/4)          // 1048576 float4 quads
#define NBLK (NVEC/256)        // 4096 blocks

#define DXd ((2.0 + 0.5) / 63.0)
#define DYd ((0.5 + 0.5) / 127.0)
#define DZd ((0.3 + 0.5) / 63.0)

// compile-time literals (imm-form FFMA, no LDC)
constexpr float c_inv2dx = (float)(1.0 / (2.0 * DXd));
constexpr float c_inv2dy = (float)(1.0 / (2.0 * DYd));
constexpr float c_inv2dz = (float)(1.0 / (2.0 * DZd));
constexpr float c_idx2   = (float)(1.0 / (DXd * DXd));
constexpr float c_idy2   = (float)(1.0 / (DYd * DYd));
constexpr float c_idz2   = (float)(1.0 / (DZd * DZd));

constexpr float c_sc_field  = (float)(1.0  / (double)(NB*4*SP));
constexpr float c_sc_ct     = (float)(10.0 / 8.0);
constexpr float c_sc_cm     = (float)(1.0  / (double)(NB*(ND-2)*(NH-2)*(NW-2)));
constexpr float c_sc_noslip = (float)(10.0 / (double)NPTS);
constexpr float c_sc_inlet  = (float)(5.0  / (double)(NB*ND*NH));
constexpr float c_sc_outlet = (float)(1.0  / (double)(NB*ND*NH));

#define INV_RE 1.0e-6f
#define OY NW
#define OZ (NH*NW)

__device__ double g_acc = 0.0;
__device__ unsigned int g_count = 0;

__device__ __forceinline__ float4 ld4(const float* p) {
    return *reinterpret_cast<const float4*>(p);
}

__global__ void __launch_bounds__(256, 4) k_loss(
    const float* __restrict__ field,
    const float* __restrict__ ct,
    const float* __restrict__ gt_field,
    const float* __restrict__ gt_ct,
    const float* __restrict__ sdf,
    float* __restrict__ out)
{
    const int vid = blockIdx.x * 256 + threadIdx.x;   // exactly NVEC threads
    const int wq = vid & 15;
    const int h  = (vid >> 4)  & (NH - 1);
    const int d  = (vid >> 11) & (ND - 1);
    const int b  = vid >> 17;

    const int sidx  = ((d * NH + h) << 6) + (wq << 2);
    const float* fb = field    + b * (4 * SP) + sidx;
    const float* gb = gt_field + b * (4 * SP) + sidx;

    float acc = 0.0f;

    if (vid < 8) {
        float dct = ct[vid] - gt_ct[vid];
        acc += c_sc_ct * dct * dct;
    }

    // velocity centers (persist): Fv[c][lane], c=0..2
    float Fv[3][4];
    #pragma unroll
    for (int c = 0; c < 3; c++) {
        float4 t = ld4(fb + c * CS);
        Fv[c][0] = t.x; Fv[c][1] = t.y; Fv[c][2] = t.z; Fv[c][3] = t.w;
    }

    // velocity MSE (gt consumed immediately)
    {
        float m = 0.0f;
        #pragma unroll
        for (int c = 0; c < 3; c++) {
            float4 g = ld4(gb + c * CS);
            float d0 = Fv[c][0] - g.x, d1 = Fv[c][1] - g.y;
            float d2 = Fv[c][2] - g.z, d3 = Fv[c][3] - g.w;
            m += d0*d0 + d1*d1 + d2*d2 + d3*d3;
        }
        acc += c_sc_field * m;
    }

    float4 sv = ld4(sdf + b * SP + sidx);
    float Sv[4] = {sv.x, sv.y, sv.z, sv.w};

    // no-slip (sdf <= 0)
    {
        float m = 0.0f;
        #pragma unroll
        for (int l = 0; l < 4; l++) {
            float q = Fv[0][l]*Fv[0][l] + Fv[1][l]*Fv[1][l] + Fv[2][l]*Fv[2][l];
            m += (Sv[l] <= 0.0f) ? q : 0.0f;
        }
        acc += c_sc_noslip * m;
    }

    // inlet / outlet
    if (wq == 0) {
        float du0 = Fv[0][0] - 1.0f;
        acc += c_sc_inlet * (du0*du0 + Fv[1][0]*Fv[1][0] + Fv[2][0]*Fv[2][0]);
    }
    if (wq == 15) {
        float a0 = Fv[0][3] - Fv[0][2];
        float a1 = Fv[1][3] - Fv[1][2];
        float a2 = Fv[2][3] - Fv[2][2];
        acc += c_sc_outlet * (a0*a0 + a1*a1 + a2*a2);
    }

    const bool yz_interior = (d >= 1) & (d <= ND - 2) & (h >= 1) & (h <= NH - 2);

    // --- pressure block: MSE + all gradients; p regs die at end of block ---
    float gpx[4], gpy[4], gpz[4];
    {
        const float* cb = fb + 3 * CS;
        float4 pc = ld4(cb);
        {
            float4 g = ld4(gb + 3 * CS);
            float d0 = pc.x - g.x, d1 = pc.y - g.y;
            float d2 = pc.z - g.z, d3 = pc.w - g.w;
            acc += c_sc_field * (d0*d0 + d1*d1 + d2*d2 + d3*d3);
        }
        if (yz_interior) {
            float Lc = (wq != 0)  ? cb[-1] : 0.0f;
            float Rc = (wq != 15) ? cb[4]  : 0.0f;
            float4 yp = ld4(cb + OY), ym = ld4(cb - OY);
            float4 zp = ld4(cb + OZ), zm = ld4(cb - OZ);
            gpy[0] = (yp.x - ym.x) * c_inv2dy;
            gpy[1] = (yp.y - ym.y) * c_inv2dy;
            gpy[2] = (yp.z - ym.z) * c_inv2dy;
            gpy[3] = (yp.w - ym.w) * c_inv2dy;
            gpz[0] = (zp.x - zm.x) * c_inv2dz;
            gpz[1] = (zp.y - zm.y) * c_inv2dz;
            gpz[2] = (zp.z - zm.z) * c_inv2dz;
            gpz[3] = (zp.w - zm.w) * c_inv2dz;
            gpx[0] = (pc.y - Lc)   * c_inv2dx;
            gpx[1] = (pc.z - pc.x) * c_inv2dx;
            gpx[2] = (pc.w - pc.y) * c_inv2dx;
            gpx[3] = (Rc   - pc.z) * c_inv2dx;
        }
    }

    // --- interior continuity + momentum, velocity channels streamed ---
    if (yz_interior) {
        float wgt[4];
        wgt[0] = (wq != 0  && Sv[0] > 0.0f) ? 1.0f : 0.0f;
        wgt[1] = (Sv[1] > 0.0f) ? 1.0f : 0.0f;
        wgt[2] = (Sv[2] > 0.0f) ? 1.0f : 0.0f;
        wgt[3] = (wq != 15 && Sv[3] > 0.0f) ? 1.0f : 0.0f;

        float div[4] = {0.0f, 0.0f, 0.0f, 0.0f};
        float msum = 0.0f;

        #pragma unroll
        for (int c = 0; c < 3; c++) {
            const float* cb = fb + c * CS;
            float Lc = (wq != 0)  ? cb[-1] : 0.0f;
            float Rc = (wq != 15) ? cb[4]  : 0.0f;

            float4 yp = ld4(cb + OY), ym = ld4(cb - OY);
            float4 zp = ld4(cb + OZ), zm = ld4(cb - OZ);

            float gy[4], sy[4], gz[4], sz[4];
            gy[0] = (yp.x - ym.x) * c_inv2dy; sy[0] = yp.x + ym.x;
            gy[1] = (yp.y - ym.y) * c_inv2dy; sy[1] = yp.y + ym.y;
            gy[2] = (yp.z - ym.z) * c_inv2dy; sy[2] = yp.z + ym.z;
            gy[3] = (yp.w - ym.w) * c_inv2dy; sy[3] = yp.w + ym.w;
            gz[0] = (zp.x - zm.x) * c_inv2dz; sz[0] = zp.x + zm.x;
            gz[1] = (zp.y - zm.y) * c_inv2dz; sz[1] = zp.y + zm.y;
            gz[2] = (zp.z - zm.z) * c_inv2dz; sz[2] = zp.z + zm.z;
            gz[3] = (zp.w - zm.w) * c_inv2dz; sz[3] = zp.w + zm.w;

            #pragma unroll
            for (int l = 0; l < 4; l++) {
                float ce = Fv[c][l];
                float xm = (l == 0) ? Lc : Fv[c][l - 1];
                float xp = (l == 3) ? Rc : Fv[c][l + 1];
                float gx = (xp - xm) * c_inv2dx;
                float lap = (xp + xm - 2.0f * ce) * c_idx2
                          + (sy[l]   - 2.0f * ce) * c_idy2
                          + (sz[l]   - 2.0f * ce) * c_idz2;
                float gp  = (c == 0) ? gpx[l] : (c == 1) ? gpy[l] : gpz[l];
                float res = Fv[0][l] * gx + Fv[1][l] * gy[l] + Fv[2][l] * gz[l]
                          + gp - INV_RE * lap;
                msum   += wgt[l] * res * res;
                div[l] += (c == 0) ? gx : (c == 1) ? gy[l] : gz[l];
            }
        }

        #pragma unroll
        for (int l = 0; l < 4; l++)
            msum += wgt[l] * div[l] * div[l];

        acc += c_sc_cm * msum;
    }

    // ---- reduction: warp shfl (f32) -> block (f64) -> global atomic ----
    #pragma unroll
    for (int o = 16; o > 0; o >>= 1)
        acc += __shfl_down_sync(0xffffffffu, acc, o);

    __shared__ double warpsum[8];
    if ((threadIdx.x & 31) == 0)
        warpsum[threadIdx.x >> 5] = (double)acc;
    __syncthreads();

    if (threadIdx.x == 0) {
        double t = 0.0;
        #pragma unroll
        for (int i = 0; i < 8; i++) t += warpsum[i];
        atomicAdd(&g_acc, t);
        __threadfence();
        unsigned int ticket = atomicAdd(&g_count, 1u);
        if (ticket == (unsigned)(gridDim.x - 1)) {
            double tot = atomicAdd(&g_acc, 0.0);
            out[0] = (float)tot;
            g_acc = 0.0;       // reset for next graph replay
            g_count = 0u;
            __threadfence();
        }
    }
}

extern "C" void kernel_launch(void* const* d_in, const int* in_sizes, int n_in,
                              void* d_out, int out_size)
{
    const float* field    = (const float*)d_in[0];
    const float* ct       = (const float*)d_in[1];
    const float* gt_field = (const float*)d_in[2];
    const float* gt_ct    = (const float*)d_in[3];
    const float* sdf      = (const float*)d_in[4];

    k_loss<<<NBLK, 256>>>(field, ct, gt_field, gt_ct, sdf, (float*)d_out);
}

// round 6
// speedup vs baseline: 1.5706x; 1.1243x over previous
#include <cuda_runtime.h>

// Shapes: field/gt_field (8,4,64,128,64) f32, ct/gt_ct (8,1) f32, sdf (8,1,64,128,64) f32.
// Output: scalar f32 total loss. Single fused kernel, float4 along W,
// channel-streamed interior, shfl-based x-edges, streaming hints on gt/sdf.

#define NB 8
#define ND 64
#define NH 128
#define NW 64
#define SP (ND*NH*NW)
#define CS SP
#define NPTS (NB*SP)
#define NVEC (NPTS/4)          // 1048576 float4 quads
#define NBLK (NVEC/256)        // 4096 blocks

#define DXd ((2.0 + 0.5) / 63.0)
#define DYd ((0.5 + 0.5) / 127.0)
#define DZd ((0.3 + 0.5) / 63.0)

constexpr float c_inv2dx = (float)(1.0 / (2.0 * DXd));
constexpr float c_inv2dy = (float)(1.0 / (2.0 * DYd));
constexpr float c_inv2dz = (float)(1.0 / (2.0 * DZd));
constexpr float c_idx2   = (float)(1.0 / (DXd * DXd));
constexpr float c_idy2   = (float)(1.0 / (DYd * DYd));
constexpr float c_idz2   = (float)(1.0 / (DZd * DZd));

constexpr float c_sc_field  = (float)(1.0  / (double)(NB*4*SP));
constexpr float c_sc_ct     = (float)(10.0 / 8.0);
constexpr float c_sc_cm     = (float)(1.0  / (double)(NB*(ND-2)*(NH-2)*(NW-2)));
constexpr float c_sc_noslip = (float)(10.0 / (double)NPTS);
constexpr float c_sc_inlet  = (float)(5.0  / (double)(NB*ND*NH));
constexpr float c_sc_outlet = (float)(1.0  / (double)(NB*ND*NH));

#define INV_RE 1.0e-6f
#define OY NW
#define OZ (NH*NW)
#define FULLMASK 0xffffffffu

__device__ double g_acc = 0.0;
__device__ unsigned int g_count = 0;

__device__ __forceinline__ float4 ld4(const float* p) {
    return *reinterpret_cast<const float4*>(p);
}
__device__ __forceinline__ float4 ld4cs(const float* p) {
    return __ldcs(reinterpret_cast<const float4*>(p));
}

__global__ void __launch_bounds__(256, 4) k_loss(
    const float* __restrict__ field,
    const float* __restrict__ ct,
    const float* __restrict__ gt_field,
    const float* __restrict__ gt_ct,
    const float* __restrict__ sdf,
    float* __restrict__ out)
{
    const int vid = blockIdx.x * 256 + threadIdx.x;   // exactly NVEC threads
    const int wq = vid & 15;
    const int h  = (vid >> 4)  & (NH - 1);
    const int d  = (vid >> 11) & (ND - 1);
    const int b  = vid >> 17;

    const int sidx  = ((d * NH + h) << 6) + (wq << 2);
    const float* fb = field    + b * (4 * SP) + sidx;
    const float* gb = gt_field + b * (4 * SP) + sidx;

    float acc = 0.0f;

    if (vid < 8) {
        float dct = ct[vid] - gt_ct[vid];
        acc += c_sc_ct * dct * dct;
    }

    // velocity centers (persist): Fv[c][lane], c=0..2
    float Fv[3][4];
    #pragma unroll
    for (int c = 0; c < 3; c++) {
        float4 t = ld4(fb + c * CS);
        Fv[c][0] = t.x; Fv[c][1] = t.y; Fv[c][2] = t.z; Fv[c][3] = t.w;
    }

    // velocity MSE (gt consumed immediately, streaming hint)
    {
        float m = 0.0f;
        #pragma unroll
        for (int c = 0; c < 3; c++) {
            float4 g = ld4cs(gb + c * CS);
            float d0 = Fv[c][0] - g.x, d1 = Fv[c][1] - g.y;
            float d2 = Fv[c][2] - g.z, d3 = Fv[c][3] - g.w;
            m += d0*d0 + d1*d1 + d2*d2 + d3*d3;
        }
        acc += c_sc_field * m;
    }

    float4 sv = ld4cs(sdf + b * SP + sidx);
    float Sv[4] = {sv.x, sv.y, sv.z, sv.w};

    // no-slip (sdf <= 0)
    {
        float m = 0.0f;
        #pragma unroll
        for (int l = 0; l < 4; l++) {
            float q = Fv[0][l]*Fv[0][l] + Fv[1][l]*Fv[1][l] + Fv[2][l]*Fv[2][l];
            m += (Sv[l] <= 0.0f) ? q : 0.0f;
        }
        acc += c_sc_noslip * m;
    }

    // inlet / outlet
    if (wq == 0) {
        float du0 = Fv[0][0] - 1.0f;
        acc += c_sc_inlet * (du0*du0 + Fv[1][0]*Fv[1][0] + Fv[2][0]*Fv[2][0]);
    }
    if (wq == 15) {
        float a0 = Fv[0][3] - Fv[0][2];
        float a1 = Fv[1][3] - Fv[1][2];
        float a2 = Fv[2][3] - Fv[2][2];
        acc += c_sc_outlet * (a0*a0 + a1*a1 + a2*a2);
    }

    const bool yz_interior = (d >= 1) & (d <= ND - 2) & (h >= 1) & (h <= NH - 2);

    // ---- x-edge neighbors via warp shuffle (uniform execution, full warp) ----
    // Lc[c] = last element of previous quad = lane-1's Fv[c][3]
    // Rc[c] = first element of next quad   = lane+1's Fv[c][0]
    // Row-crossing lanes (wq==0 for Lc, wq==15 for Rc) produce garbage that is
    // zero-masked by wgt[] below.
    float Lcs[3], Rcs[3];
    #pragma unroll
    for (int c = 0; c < 3; c++) {
        Lcs[c] = __shfl_up_sync  (FULLMASK, Fv[c][3], 1);
        Rcs[c] = __shfl_down_sync(FULLMASK, Fv[c][0], 1);
    }

    // --- pressure block: MSE + gradients; p regs die at end of block ---
    float gpx[4], gpy[4], gpz[4];
    {
        const float* cb = fb + 3 * CS;
        float4 pc = ld4(cb);
        float pL = __shfl_up_sync  (FULLMASK, pc.w, 1);
        float pR = __shfl_down_sync(FULLMASK, pc.x, 1);
        {
            float4 g = ld4cs(gb + 3 * CS);
            float d0 = pc.x - g.x, d1 = pc.y - g.y;
            float d2 = pc.z - g.z, d3 = pc.w - g.w;
            acc += c_sc_field * (d0*d0 + d1*d1 + d2*d2 + d3*d3);
        }
        if (yz_interior) {
            float4 yp = ld4(cb + OY), ym = ld4(cb - OY);
            float4 zp = ld4(cb + OZ), zm = ld4(cb - OZ);
            gpy[0] = (yp.x - ym.x) * c_inv2dy;
            gpy[1] = (yp.y - ym.y) * c_inv2dy;
            gpy[2] = (yp.z - ym.z) * c_inv2dy;
            gpy[3] = (yp.w - ym.w) * c_inv2dy;
            gpz[0] = (zp.x - zm.x) * c_inv2dz;
            gpz[1] = (zp.y - zm.y) * c_inv2dz;
            gpz[2] = (zp.z - zm.z) * c_inv2dz;
            gpz[3] = (zp.w - zm.w) * c_inv2dz;
            gpx[0] = (pc.y - pL)   * c_inv2dx;
            gpx[1] = (pc.z - pc.x) * c_inv2dx;
            gpx[2] = (pc.w - pc.y) * c_inv2dx;
            gpx[3] = (pR   - pc.z) * c_inv2dx;
        }
    }

    // --- interior continuity + momentum, velocity channels streamed ---
    if (yz_interior) {
        float wgt[4];
        wgt[0] = (wq != 0  && Sv[0] > 0.0f) ? 1.0f : 0.0f;
        wgt[1] = (Sv[1] > 0.0f) ? 1.0f : 0.0f;
        wgt[2] = (Sv[2] > 0.0f) ? 1.0f : 0.0f;
        wgt[3] = (wq != 15 && Sv[3] > 0.0f) ? 1.0f : 0.0f;

        float div[4] = {0.0f, 0.0f, 0.0f, 0.0f};
        float msum = 0.0f;

        #pragma unroll
        for (int c = 0; c < 3; c++) {
            const float* cb = fb + c * CS;
            float4 yp = ld4(cb + OY), ym = ld4(cb - OY);
            float4 zp = ld4(cb + OZ), zm = ld4(cb - OZ);

            float gy[4], sy[4], gz[4], sz[4];
            gy[0] = (yp.x - ym.x) * c_inv2dy; sy[0] = yp.x + ym.x;
            gy[1] = (yp.y - ym.y) * c_inv2dy; sy[1] = yp.y + ym.y;
            gy[2] = (yp.z - ym.z) * c_inv2dy; sy[2] = yp.z + ym.z;
            gy[3] = (yp.w - ym.w) * c_inv2dy; sy[3] = yp.w + ym.w;
            gz[0] = (zp.x - zm.x) * c_inv2dz; sz[0] = zp.x + zm.x;
            gz[1] = (zp.y - zm.y) * c_inv2dz; sz[1] = zp.y + zm.y;
            gz[2] = (zp.z - zm.z) * c_inv2dz; sz[2] = zp.z + zm.z;
            gz[3] = (zp.w - zm.w) * c_inv2dz; sz[3] = zp.w + zm.w;

            #pragma unroll
            for (int l = 0; l < 4; l++) {
                float ce = Fv[c][l];
                float xm = (l == 0) ? Lcs[c] : Fv[c][l - 1];
                float xp = (l == 3) ? Rcs[c] : Fv[c][l + 1];
                float gx = (xp - xm) * c_inv2dx;
                float lap = (xp + xm - 2.0f * ce) * c_idx2
                          + (sy[l]   - 2.0f * ce) * c_idy2
                          + (sz[l]   - 2.0f * ce) * c_idz2;
                float gp  = (c == 0) ? gpx[l] : (c == 1) ? gpy[l] : gpz[l];
                float res = Fv[0][l] * gx + Fv[1][l] * gy[l] + Fv[2][l] * gz[l]
                          + gp - INV_RE * lap;
                msum   += wgt[l] * res * res;
                div[l] += (c == 0) ? gx : (c == 1) ? gy[l] : gz[l];
            }
        }

        #pragma unroll
        for (int l = 0; l < 4; l++)
            msum += wgt[l] * div[l] * div[l];

        acc += c_sc_cm * msum;
    }

    // ---- reduction: warp shfl (f32) -> block (f64) -> global atomic ----
    #pragma unroll
    for (int o = 16; o > 0; o >>= 1)
        acc += __shfl_down_sync(FULLMASK, acc, o);

    __shared__ double warpsum[8];
    if ((threadIdx.x & 31) == 0)
        warpsum[threadIdx.x >> 5] = (double)acc;
    __syncthreads();

    if (threadIdx.x == 0) {
        double t = 0.0;
        #pragma unroll
        for (int i = 0; i < 8; i++) t += warpsum[i];
        atomicAdd(&g_acc, t);
        __threadfence();
        unsigned int ticket = atomicAdd(&g_count, 1u);
        if (ticket == (unsigned)(gridDim.x - 1)) {
            double tot = atomicAdd(&g_acc, 0.0);
            out[0] = (float)tot;
            g_acc = 0.0;       // reset for next graph replay
            g_count = 0u;
            __threadfence();
        }
    }
}

extern "C" void kernel_launch(void* const* d_in, const int* in_sizes, int n_in,
                              void* d_out, int out_size)
{
    const float* field    = (const float*)d_in[0];
    const float* ct       = (const float*)d_in[1];
    const float* gt_field = (const float*)d_in[2];
    const float* gt_ct    = (const float*)d_in[3];
    const float* sdf      = (const float*)d_in[4];

    k_loss<<<NBLK, 256>>>(field, ct, gt_field, gt_ct, sdf, (float*)d_out);
}